// round 5
// baseline (speedup 1.0000x reference)
#include <cuda_runtime.h>
#include <math.h>

#define BSZ   256
#define TSZ   600
#define HID   512
#define EMBD  50
#define VOC   83
#define NGATE (3*HID)

// ---------------- scratch (device globals; no allocation) ----------------
__device__ float d_hadd[BSZ*HID];        // hidden@W_hp + b_hp + b_ep
__device__ float d_scores[BSZ*TSZ];      // attention logits
__device__ float d_context[BSZ*HID];     // raw context
__device__ float d_ctxp[BSZ*250];        // context @ W_cs + b_cs
__device__ float d_indec[BSZ*300];       // [embed(50), ctxp(250)]
__device__ float d_gi[BSZ*NGATE];
__device__ float d_gh[BSZ*NGATE];

// ---------------- generic guarded SGEMM: C = A@W + bias1 (+bias2) --------
// A: [M,K] row-major, W: [K,N] row-major. 64x64 tile, BK=8, 256 thr, 4x4 micro.
__global__ void sgemm_bias(const float* __restrict__ A, const float* __restrict__ W,
                           const float* __restrict__ bias1, const float* __restrict__ bias2,
                           float* __restrict__ C, int M, int N, int K) {
    __shared__ float As[8][64];
    __shared__ float Bs[8][64];
    int tid = threadIdx.x;
    int tx = tid & 15, ty = tid >> 4;
    int row0 = blockIdx.y * 64, col0 = blockIdx.x * 64;
    float acc[4][4] = {};
    for (int k0 = 0; k0 < K; k0 += 8) {
        for (int i = tid; i < 64*8; i += 256) {
            int m = i >> 3, kk = i & 7;
            int gr = row0 + m, gk = k0 + kk;
            As[kk][m] = (gr < M && gk < K) ? A[gr*K + gk] : 0.f;
        }
        for (int i = tid; i < 8*64; i += 256) {
            int kk = i >> 6, n = i & 63;
            int gk = k0 + kk, gc = col0 + n;
            Bs[kk][n] = (gk < K && gc < N) ? W[gk*N + gc] : 0.f;
        }
        __syncthreads();
        #pragma unroll
        for (int kk = 0; kk < 8; kk++) {
            float a[4], b[4];
            #pragma unroll
            for (int i = 0; i < 4; i++) a[i] = As[kk][ty*4+i];
            #pragma unroll
            for (int j = 0; j < 4; j++) b[j] = Bs[kk][tx*4+j];
            #pragma unroll
            for (int i = 0; i < 4; i++)
                #pragma unroll
                for (int j = 0; j < 4; j++) acc[i][j] += a[i]*b[j];
        }
        __syncthreads();
    }
    #pragma unroll
    for (int i = 0; i < 4; i++) {
        int gr = row0 + ty*4 + i; if (gr >= M) continue;
        #pragma unroll
        for (int j = 0; j < 4; j++) {
            int gc = col0 + tx*4 + j; if (gc >= N) continue;
            float v = acc[i][j] + bias1[gc];
            if (bias2) v += bias2[gc];
            C[gr*N + gc] = v;
        }
    }
}

// ---------------- init scores with b_v ----------------
__global__ void init_scores(const float* __restrict__ b_v) {
    int i = blockIdx.x * blockDim.x + threadIdx.x;
    if (i < BSZ*TSZ) d_scores[i] = b_v[0];
}

// ---------------- big fused kernel --------------------
// scores[b,t] += sum_j w_v[j] * tanh( enc[t,b,:]@W_ep[:,j] + hadd[b,j] )
// rows r = t*256 + b (enc is [T,B,H] row-major). 128x64 tile, BK=16, 256 thr, 8x4 micro.
#define ABM 128
#define ABN 64
#define ABK 16
__global__ void attn_score_kernel(const float* __restrict__ enc,
                                  const float* __restrict__ W_ep,
                                  const float* __restrict__ w_v) {
    __shared__ float As[ABK][ABM + 4];   // stride 132 floats
    __shared__ float Bs[ABK][ABN];
    int tid = threadIdx.x;
    int tx = tid & 15, ty = tid >> 4;
    int row0 = blockIdx.y * ABM;
    int col0 = blockIdx.x * ABN;
    const float* Ablk = enc + (long long)row0 * HID;
    float acc[8][4] = {};

    for (int k0 = 0; k0 < HID; k0 += ABK) {
        // A tile: 128 rows x 16 k = 512 float4; 2 per thread
        #pragma unroll
        for (int l = 0; l < 2; l++) {
            int idx = tid + l*256;
            int m  = idx >> 2;
            int kq = (idx & 3) << 2;
            float4 v = *reinterpret_cast<const float4*>(Ablk + m*HID + k0 + kq);
            As[kq+0][m] = v.x; As[kq+1][m] = v.y; As[kq+2][m] = v.z; As[kq+3][m] = v.w;
        }
        // B tile: 16 x 64 = 256 float4; 1 per thread
        {
            int kk = tid >> 4;
            int c4 = (tid & 15) << 2;
            float4 v = *reinterpret_cast<const float4*>(W_ep + (k0+kk)*HID + col0 + c4);
            *reinterpret_cast<float4*>(&Bs[kk][c4]) = v;
        }
        __syncthreads();
        #pragma unroll
        for (int kk = 0; kk < ABK; kk++) {
            float a[8], b[4];
            #pragma unroll
            for (int i = 0; i < 8; i++) a[i] = As[kk][ty*8+i];
            #pragma unroll
            for (int j = 0; j < 4; j++) b[j] = Bs[kk][tx*4+j];
            #pragma unroll
            for (int i = 0; i < 8; i++)
                #pragma unroll
                for (int j = 0; j < 4; j++) acc[i][j] += a[i]*b[j];
        }
        __syncthreads();
    }

    // epilogue: tanh + dot with w_v, half-warp reduce, 1 atomic per row
    float wv[4];
    #pragma unroll
    for (int j = 0; j < 4; j++) wv[j] = w_v[col0 + tx*4 + j];
    #pragma unroll
    for (int i = 0; i < 8; i++) {
        int r = row0 + ty*8 + i;
        int b = r & 255, t = r >> 8;
        const float* ha = d_hadd + b*HID + col0 + tx*4;
        float p = 0.f;
        #pragma unroll
        for (int j = 0; j < 4; j++)
            p += wv[j] * tanhf(acc[i][j] + ha[j]);
        p += __shfl_down_sync(0xffffffffu, p, 8, 16);
        p += __shfl_down_sync(0xffffffffu, p, 4, 16);
        p += __shfl_down_sync(0xffffffffu, p, 2, 16);
        p += __shfl_down_sync(0xffffffffu, p, 1, 16);
        if (tx == 0) atomicAdd(&d_scores[b*TSZ + t], p);
    }
}

// ---------------- softmax over T -> attn_weights (to d_out) ----------------
__global__ void softmax_attn(float* __restrict__ out_aw) {
    int b = blockIdx.x;
    int tid = threadIdx.x;
    __shared__ float red[256];
    float m = -1e30f;
    for (int t = tid; t < TSZ; t += 256) m = fmaxf(m, d_scores[b*TSZ + t]);
    red[tid] = m; __syncthreads();
    for (int s = 128; s > 0; s >>= 1) {
        if (tid < s) red[tid] = fmaxf(red[tid], red[tid+s]);
        __syncthreads();
    }
    m = red[0]; __syncthreads();
    float sum = 0.f;
    for (int t = tid; t < TSZ; t += 256) {
        float e = expf(d_scores[b*TSZ + t] - m);
        d_scores[b*TSZ + t] = e;
        sum += e;
    }
    red[tid] = sum; __syncthreads();
    for (int s = 128; s > 0; s >>= 1) {
        if (tid < s) red[tid] += red[tid+s];
        __syncthreads();
    }
    float inv = 1.f / red[0];
    for (int t = tid; t < TSZ; t += 256)
        out_aw[b*TSZ + t] = d_scores[b*TSZ + t] * inv;
}

// ---------------- context[b,h] = sum_t enc[t,b,h] * aw[b,t] ----------------
__global__ void context_kernel(const float* __restrict__ enc, const float* __restrict__ aw) {
    int b = blockIdx.x;
    int h = threadIdx.x;           // 512 threads
    __shared__ float saw[TSZ];
    for (int t = h; t < TSZ; t += 512) saw[t] = aw[b*TSZ + t];
    __syncthreads();
    float s = 0.f;
    const float* base = enc + b*HID + h;
    for (int t = 0; t < TSZ; t++)
        s += base[(long long)t * BSZ * HID] * saw[t];
    d_context[b*HID + h] = s;
}

// ---------------- argmax(in_char) -> embed, concat with ctxp --------------
__global__ void build_indec(const float* __restrict__ in_char, const float* __restrict__ emb) {
    int b = blockIdx.x;
    __shared__ int s_idx;
    if (threadIdx.x < 32) {
        int lane = threadIdx.x;
        float best = -1e30f; int bi = 0;
        for (int c = lane; c < VOC; c += 32) {
            float v = in_char[b*VOC + c];
            if (v > best) { best = v; bi = c; }
        }
        for (int off = 16; off; off >>= 1) {
            float ob = __shfl_down_sync(0xffffffffu, best, off);
            int   oi = __shfl_down_sync(0xffffffffu, bi, off);
            if (ob > best || (ob == best && oi < bi)) { best = ob; bi = oi; }
        }
        if (lane == 0) s_idx = bi;
    }
    __syncthreads();
    int top = s_idx;
    for (int i = threadIdx.x; i < 300; i += 64)
        d_indec[b*300 + i] = (i < EMBD) ? emb[top*EMBD + i] : d_ctxp[b*250 + (i - EMBD)];
}

// ---------------- GRU gate fusion; writes new_h to d_out ----------------
__global__ void gru_gate(const float* __restrict__ hidden, float* __restrict__ out_h) {
    int idx = blockIdx.x * blockDim.x + threadIdx.x;
    if (idx >= BSZ*HID) return;
    int b = idx >> 9, h = idx & 511;
    const float* gi = d_gi + b*NGATE;
    const float* gh = d_gh + b*NGATE;
    float ir = gi[h],        hr = gh[h];
    float iz = gi[HID+h],    hz = gh[HID+h];
    float in_ = gi[2*HID+h], hn = gh[2*HID+h];
    float r = 1.f / (1.f + expf(-(ir + hr)));
    float z = 1.f / (1.f + expf(-(iz + hz)));
    float n = tanhf(in_ + r * hn);
    float hp = hidden[idx];
    out_h[idx] = (1.f - z) * n + z * hp;
}

// ---------------- output = softmax(new_h @ W_out + b_out) ----------------
__global__ void out_softmax(const float* __restrict__ newh, const float* __restrict__ W_out,
                            const float* __restrict__ b_out, float* __restrict__ out) {
    int b = blockIdx.x;
    int tid = threadIdx.x;       // 128
    __shared__ float sh[HID];
    __shared__ float logit[VOC];
    __shared__ float s_max, s_inv;
    for (int k = tid; k < HID; k += 128) sh[k] = newh[b*HID + k];
    __syncthreads();
    if (tid < VOC) {
        float s = b_out[tid];
        for (int k = 0; k < HID; k++) s += sh[k] * W_out[k*VOC + tid];
        logit[tid] = s;
    }
    __syncthreads();
    if (tid == 0) {
        float m = -1e30f;
        for (int c = 0; c < VOC; c++) m = fmaxf(m, logit[c]);
        float sum = 0.f;
        for (int c = 0; c < VOC; c++) sum += expf(logit[c] - m);
        s_max = m; s_inv = 1.f / sum;
    }
    __syncthreads();
    if (tid < VOC)
        out[b*VOC + tid] = expf(logit[tid] - s_max) * s_inv;
}

// ---------------- launch ----------------
extern "C" void kernel_launch(void* const* d_in, const int* in_sizes, int n_in,
                              void* d_out, int out_size) {
    const float* in_char = (const float*)d_in[0];
    const float* hidden  = (const float*)d_in[1];
    const float* enc     = (const float*)d_in[2];
    const float* W_hp    = (const float*)d_in[3];
    const float* b_hp    = (const float*)d_in[4];
    const float* W_ep    = (const float*)d_in[5];
    const float* b_ep    = (const float*)d_in[6];
    const float* w_v     = (const float*)d_in[7];
    const float* b_v     = (const float*)d_in[8];
    const float* W_cs    = (const float*)d_in[9];
    const float* b_cs    = (const float*)d_in[10];
    const float* emb     = (const float*)d_in[11];
    const float* W_ih    = (const float*)d_in[12];
    const float* b_ih    = (const float*)d_in[13];
    const float* W_hh    = (const float*)d_in[14];
    const float* b_hh    = (const float*)d_in[15];
    const float* W_out   = (const float*)d_in[16];
    const float* b_out   = (const float*)d_in[17];

    float* out = (float*)d_out;
    float* out_output = out;                       // 256*83
    float* out_newh   = out + BSZ*VOC;             // 256*512
    float* out_aw     = out + BSZ*VOC + BSZ*HID;   // 256*600

    float* p_hadd, *p_ctx, *p_ctxp, *p_indec, *p_gi, *p_gh;
    cudaGetSymbolAddress((void**)&p_hadd,  d_hadd);
    cudaGetSymbolAddress((void**)&p_ctx,   d_context);
    cudaGetSymbolAddress((void**)&p_ctxp,  d_ctxp);
    cudaGetSymbolAddress((void**)&p_indec, d_indec);
    cudaGetSymbolAddress((void**)&p_gi,    d_gi);
    cudaGetSymbolAddress((void**)&p_gh,    d_gh);

    // 1. scores init with b_v
    init_scores<<<(BSZ*TSZ + 255)/256, 256>>>(b_v);

    // 2. hadd = hidden@W_hp + b_hp + b_ep
    {
        dim3 g(HID/64, BSZ/64);
        sgemm_bias<<<g, 256>>>(hidden, W_hp, b_hp, b_ep, p_hadd, BSZ, HID, HID);
    }

    // 3. gh = hidden@W_hh + b_hh (independent, do it early)
    {
        dim3 g(NGATE/64, BSZ/64);
        sgemm_bias<<<g, 256>>>(hidden, W_hh, b_hh, nullptr, p_gh, BSZ, NGATE, HID);
    }

    // 4. big fused attention-score GEMM
    {
        dim3 g(HID/ABN, (BSZ*TSZ)/ABM);
        attn_score_kernel<<<g, 256>>>(enc, W_ep, w_v);
    }

    // 5. softmax -> attn_weights (written into d_out)
    softmax_attn<<<BSZ, 256>>>(out_aw);

    // 6. context = weighted sum of enc
    context_kernel<<<BSZ, HID>>>(enc, out_aw);

    // 7. ctxp = context@W_cs + b_cs
    {
        dim3 g((250 + 63)/64, BSZ/64);
        sgemm_bias<<<g, 256>>>(p_ctx, W_cs, b_cs, nullptr, p_ctxp, BSZ, 250, HID);
    }

    // 8. in_dec = [emb[argmax(in_char)], ctxp]
    build_indec<<<BSZ, 64>>>(in_char, emb);

    // 9. gi = in_dec@W_ih + b_ih
    {
        dim3 g(NGATE/64, BSZ/64);
        sgemm_bias<<<g, 256>>>(p_indec, W_ih, b_ih, nullptr, p_gi, BSZ, NGATE, 300);
    }

    // 10. GRU gates -> new_h (into d_out)
    gru_gate<<<(BSZ*HID)/256, 256>>>(hidden, out_newh);

    // 11. output = softmax(new_h @ W_out + b_out)
    out_softmax<<<BSZ, 128>>>(out_newh, W_out, b_out, out_output);
}

// round 11
// speedup vs baseline: 2.0516x; 2.0516x over previous
#include <cuda_runtime.h>
#include <cstdint>
#include <math.h>

#define BSZ   256
#define TSZ   600
#define HID   512
#define EMBD  50
#define VOC   83
#define NGATE (3*HID)

// ---------------- scratch (device globals; no allocation) ----------------
__device__ float d_hadd[BSZ*HID];
__device__ float d_scores[BSZ*TSZ];
__device__ float d_context[BSZ*HID];
__device__ float d_ctxp[BSZ*250];
__device__ float d_indec[BSZ*300];
__device__ float d_gi[BSZ*NGATE];
__device__ float d_gh[BSZ*NGATE];
__device__ float d_WepT[HID*HID];   // W_ep transposed: [n][k]

// ================= PTX helpers (plain sm_80+ instructions only) =================
__device__ __forceinline__ uint32_t smem_u32(const void* p) {
    uint32_t a;
    asm("{ .reg .u64 t; cvta.to.shared.u64 t, %1; cvt.u32.u64 %0, t; }" : "=r"(a) : "l"(p));
    return a;
}
__device__ __forceinline__ float tanh_fast(float x) {
    float y; asm("tanh.approx.f32 %0, %1;" : "=f"(y) : "f"(x)); return y;
}
__device__ __forceinline__ uint32_t to_tf32(float x) {
    uint32_t r; asm("cvt.rna.tf32.f32 %0, %1;" : "=r"(r) : "f"(x)); return r;
}
#define CP_ASYNC16(dst, src) \
    asm volatile("cp.async.cg.shared.global [%0], [%1], 16;" :: "r"(dst), "l"(src) : "memory")
#define CP_COMMIT()  asm volatile("cp.async.commit_group;" ::: "memory")
#define CP_WAIT(n)   asm volatile("cp.async.wait_group %0;" :: "n"(n) : "memory")

__device__ __forceinline__ void mma_tf32(float* c, const uint32_t* a, const uint32_t* b) {
    asm volatile(
        "mma.sync.aligned.m16n8k8.row.col.f32.tf32.tf32.f32 "
        "{%0,%1,%2,%3}, {%4,%5,%6,%7}, {%8,%9}, {%0,%1,%2,%3};"
        : "+f"(c[0]), "+f"(c[1]), "+f"(c[2]), "+f"(c[3])
        : "r"(a[0]), "r"(a[1]), "r"(a[2]), "r"(a[3]), "r"(b[0]), "r"(b[1]));
}

// ================= attention tf32 mma.sync kernel =================
// scores[b,t] = sum_n w_v[n]*tanh( (enc@W_ep)[row,n] + hadd[b,n] ), row = t*256+b
// CTA: 128 rows x 128 cols, K=512. Warp grid 4(m) x 2(n); warp tile 32x64.
#define KCH   32
#define PADK  36                        // 32 + 4 floats: conflict-free fragment LDS
#define STG_F (128*PADK)                // floats per stage per operand (4608)
#define SM_PART_OFF (4*STG_F)           // 128 floats of cross-warp partials
#define ATTN_SMEM ((4*STG_F + 128) * 4) // 74240 bytes

__device__ __forceinline__ void load_tile32(const float* __restrict__ src,
                                            uint32_t dst_base, int tid) {
    // 128 rows x 32 floats (16KB), 4x cp.async 16B per thread
    #pragma unroll
    for (int l = 0; l < 4; l++) {
        int i = tid + l*256;
        int r = i >> 3, j = i & 7;
        CP_ASYNC16(dst_base + (uint32_t)(r*PADK + j*4)*4, src + (size_t)r*HID + j*4);
    }
}

__global__ void __launch_bounds__(256, 2) attn_mma_kernel(const float* __restrict__ enc,
                                                          const float* __restrict__ w_v) {
    extern __shared__ float smf[];
    uint32_t sb = smem_u32(smf);
    int tid = threadIdx.x, wid = tid >> 5, lane = tid & 31;
    int wm = wid & 3, wn = wid >> 2;
    int g = lane >> 2, t4 = lane & 3;

    int row0 = blockIdx.x * 128;        // rows in flattened (t*256+b) space
    int n0   = blockIdx.y * 128;
    const float* Asrc = enc + (size_t)row0 * HID;
    const float* Bsrc = d_WepT + (size_t)n0 * HID;

    uint32_t sA[2] = { sb, sb + STG_F*4 };
    uint32_t sB[2] = { sb + 2*STG_F*4, sb + 3*STG_F*4 };
    float* fA[2] = { smf, smf + STG_F };
    float* fB[2] = { smf + 2*STG_F, smf + 3*STG_F };

    float acc[2][8][4];
    #pragma unroll
    for (int mt = 0; mt < 2; mt++)
        #pragma unroll
        for (int nt = 0; nt < 8; nt++)
            #pragma unroll
            for (int q = 0; q < 4; q++) acc[mt][nt][q] = 0.f;

    // prologue: chunk 0
    load_tile32(Asrc, sA[0], tid);
    load_tile32(Bsrc, sB[0], tid);
    CP_COMMIT();

    for (int c = 0; c < HID/KCH; c++) {
        int cur = c & 1;
        if (c + 1 < HID/KCH) {
            int nxt = cur ^ 1;
            load_tile32(Asrc + (c+1)*KCH, sA[nxt], tid);
            load_tile32(Bsrc + (c+1)*KCH, sB[nxt], tid);
            CP_COMMIT();
            CP_WAIT(1);
        } else {
            CP_WAIT(0);
        }
        __syncthreads();

        const float* A = fA[cur];
        const float* B = fB[cur];
        #pragma unroll
        for (int k8 = 0; k8 < 4; k8++) {
            int kb = k8*8;
            uint32_t af[2][4], bf[8][2];
            #pragma unroll
            for (int mt = 0; mt < 2; mt++) {
                int m = wm*32 + mt*16;
                af[mt][0] = to_tf32(A[(m + g    )*PADK + kb + t4    ]);
                af[mt][1] = to_tf32(A[(m + 8 + g)*PADK + kb + t4    ]);
                af[mt][2] = to_tf32(A[(m + g    )*PADK + kb + t4 + 4]);
                af[mt][3] = to_tf32(A[(m + 8 + g)*PADK + kb + t4 + 4]);
            }
            #pragma unroll
            for (int nt = 0; nt < 8; nt++) {
                int n = wn*64 + nt*8;
                bf[nt][0] = to_tf32(B[(n + g)*PADK + kb + t4    ]);
                bf[nt][1] = to_tf32(B[(n + g)*PADK + kb + t4 + 4]);
            }
            #pragma unroll
            for (int mt = 0; mt < 2; mt++)
                #pragma unroll
                for (int nt = 0; nt < 8; nt++)
                    mma_tf32(acc[mt][nt], af[mt], bf[nt]);
        }
        __syncthreads();
    }

    // ---- fused epilogue: tanh + w_v dot, reduce, atomicAdd into d_scores ----
    {
        float2 wv2[8];
        #pragma unroll
        for (int nt = 0; nt < 8; nt++)
            wv2[nt] = *(const float2*)(w_v + n0 + wn*64 + nt*8 + 2*t4);

        float p[4];
        int rows[4], bs[4];
        int t = row0 >> 8;
        #pragma unroll
        for (int mt = 0; mt < 2; mt++) {
            #pragma unroll
            for (int hi = 0; hi < 2; hi++) {
                int r = wm*32 + mt*16 + hi*8 + g;
                int b = (row0 & 255) + r;
                const float* hb = d_hadd + b*HID + n0 + wn*64;
                float s = 0.f;
                #pragma unroll
                for (int nt = 0; nt < 8; nt++) {
                    float2 h2 = *(const float2*)(hb + nt*8 + 2*t4);
                    s += wv2[nt].x * tanh_fast(acc[mt][nt][hi*2+0] + h2.x);
                    s += wv2[nt].y * tanh_fast(acc[mt][nt][hi*2+1] + h2.y);
                }
                p[mt*2+hi] = s;
                rows[mt*2+hi] = r;
                bs[mt*2+hi] = b;
            }
        }
        #pragma unroll
        for (int j = 0; j < 4; j++) {
            p[j] += __shfl_down_sync(0xffffffffu, p[j], 2, 4);
            p[j] += __shfl_down_sync(0xffffffffu, p[j], 1, 4);
        }
        float* part = smf + SM_PART_OFF;
        if (wn == 1 && t4 == 0) {
            #pragma unroll
            for (int j = 0; j < 4; j++) part[rows[j]] = p[j];
        }
        __syncthreads();
        if (wn == 0 && t4 == 0) {
            #pragma unroll
            for (int j = 0; j < 4; j++)
                atomicAdd(&d_scores[bs[j]*TSZ + t], p[j] + part[rows[j]]);
        }
    }
}

// ---------------- prep: transpose W_ep -> d_WepT ----------------
__global__ void prep_wepT(const float* __restrict__ W) {
    __shared__ float t[32][33];
    int bx = blockIdx.x & 15;    // n tile
    int by = blockIdx.x >> 4;    // k tile
    int tx = threadIdx.x & 31, ty = threadIdx.x >> 5;   // 32x8
    #pragma unroll
    for (int i = 0; i < 4; i++)
        t[ty + 8*i][tx] = W[(by*32 + ty + 8*i)*HID + bx*32 + tx];
    __syncthreads();
    #pragma unroll
    for (int i = 0; i < 4; i++)
        d_WepT[(bx*32 + ty + 8*i)*HID + by*32 + tx] = t[tx][ty + 8*i];
}

__global__ void zero_scores() {
    int i = blockIdx.x * blockDim.x + threadIdx.x;
    if (i < BSZ*TSZ) d_scores[i] = 0.f;
}
__global__ void zero_ctx() {
    int i = blockIdx.x * blockDim.x + threadIdx.x;
    if (i < BSZ*HID) d_context[i] = 0.f;
}

// ---------------- generic guarded SGEMM ----------------
__global__ void sgemm_bias(const float* __restrict__ A, const float* __restrict__ W,
                           const float* __restrict__ bias1, const float* __restrict__ bias2,
                           float* __restrict__ C, int M, int N, int K) {
    __shared__ float As[8][64];
    __shared__ float Bs[8][64];
    int tid = threadIdx.x;
    int tx = tid & 15, ty = tid >> 4;
    int row0 = blockIdx.y * 64, col0 = blockIdx.x * 64;
    float acc[4][4] = {};
    for (int k0 = 0; k0 < K; k0 += 8) {
        for (int i = tid; i < 64*8; i += 256) {
            int m = i >> 3, kk = i & 7;
            int gr = row0 + m, gk = k0 + kk;
            As[kk][m] = (gr < M && gk < K) ? A[gr*K + gk] : 0.f;
        }
        for (int i = tid; i < 8*64; i += 256) {
            int kk = i >> 6, n = i & 63;
            int gk = k0 + kk, gc = col0 + n;
            Bs[kk][n] = (gk < K && gc < N) ? W[gk*N + gc] : 0.f;
        }
        __syncthreads();
        #pragma unroll
        for (int kk = 0; kk < 8; kk++) {
            float a[4], b[4];
            #pragma unroll
            for (int i = 0; i < 4; i++) a[i] = As[kk][ty*4+i];
            #pragma unroll
            for (int j = 0; j < 4; j++) b[j] = Bs[kk][tx*4+j];
            #pragma unroll
            for (int i = 0; i < 4; i++)
                #pragma unroll
                for (int j = 0; j < 4; j++) acc[i][j] += a[i]*b[j];
        }
        __syncthreads();
    }
    #pragma unroll
    for (int i = 0; i < 4; i++) {
        int gr = row0 + ty*4 + i; if (gr >= M) continue;
        #pragma unroll
        for (int j = 0; j < 4; j++) {
            int gc = col0 + tx*4 + j; if (gc >= N) continue;
            float v = acc[i][j] + bias1[gc];
            if (bias2) v += bias2[gc];
            C[gr*N + gc] = v;
        }
    }
}

// ---------------- softmax over T -> attn_weights ----------------
__global__ void softmax_attn(float* __restrict__ out_aw) {
    int b = blockIdx.x;
    int tid = threadIdx.x;
    __shared__ float red[256];
    float m = -1e30f;
    for (int t = tid; t < TSZ; t += 256) m = fmaxf(m, d_scores[b*TSZ + t]);
    red[tid] = m; __syncthreads();
    for (int s = 128; s > 0; s >>= 1) {
        if (tid < s) red[tid] = fmaxf(red[tid], red[tid+s]);
        __syncthreads();
    }
    m = red[0]; __syncthreads();
    float sum = 0.f;
    for (int t = tid; t < TSZ; t += 256) {
        float e = expf(d_scores[b*TSZ + t] - m);
        d_scores[b*TSZ + t] = e;
        sum += e;
    }
    red[tid] = sum; __syncthreads();
    for (int s = 128; s > 0; s >>= 1) {
        if (tid < s) red[tid] += red[tid+s];
        __syncthreads();
    }
    float inv = 1.f / red[0];
    for (int t = tid; t < TSZ; t += 256)
        out_aw[b*TSZ + t] = d_scores[b*TSZ + t] * inv;
}

// ---------------- context: 4-way split over T with atomics ----------------
__global__ void context_kernel(const float* __restrict__ enc, const float* __restrict__ aw) {
    int b = blockIdx.x, tc = blockIdx.y;
    int h = threadIdx.x;             // 512
    __shared__ float saw[150];
    if (h < 150) saw[h] = aw[b*TSZ + tc*150 + h];
    __syncthreads();
    const float* base = enc + (size_t)(tc*150)*BSZ*HID + b*HID + h;
    float s0 = 0.f, s1 = 0.f;
    for (int t = 0; t < 150; t += 2) {
        s0 += base[(size_t)t*BSZ*HID] * saw[t];
        s1 += base[(size_t)(t+1)*BSZ*HID] * saw[t+1];
    }
    atomicAdd(&d_context[b*HID + h], s0 + s1);
}

// ---------------- argmax/embed/concat ----------------
__global__ void build_indec(const float* __restrict__ in_char, const float* __restrict__ emb) {
    int b = blockIdx.x;
    __shared__ int s_idx;
    if (threadIdx.x < 32) {
        int lane = threadIdx.x;
        float best = -1e30f; int bi = 0;
        for (int c = lane; c < VOC; c += 32) {
            float v = in_char[b*VOC + c];
            if (v > best) { best = v; bi = c; }
        }
        for (int off = 16; off; off >>= 1) {
            float ob = __shfl_down_sync(0xffffffffu, best, off);
            int   oi = __shfl_down_sync(0xffffffffu, bi, off);
            if (ob > best || (ob == best && oi < bi)) { best = ob; bi = oi; }
        }
        if (lane == 0) s_idx = bi;
    }
    __syncthreads();
    int top = s_idx;
    for (int i = threadIdx.x; i < 300; i += 64)
        d_indec[b*300 + i] = (i < EMBD) ? emb[top*EMBD + i] : d_ctxp[b*250 + (i - EMBD)];
}

// ---------------- GRU gate fusion ----------------
__global__ void gru_gate(const float* __restrict__ hidden, float* __restrict__ out_h) {
    int idx = blockIdx.x * blockDim.x + threadIdx.x;
    if (idx >= BSZ*HID) return;
    int b = idx >> 9, h = idx & 511;
    const float* gi = d_gi + b*NGATE;
    const float* gh = d_gh + b*NGATE;
    float ir = gi[h],        hr = gh[h];
    float iz = gi[HID+h],    hz = gh[HID+h];
    float in_ = gi[2*HID+h], hn = gh[2*HID+h];
    float r = 1.f / (1.f + expf(-(ir + hr)));
    float z = 1.f / (1.f + expf(-(iz + hz)));
    float n = tanhf(in_ + r * hn);
    float hp = hidden[idx];
    out_h[idx] = (1.f - z) * n + z * hp;
}

// ---------------- output softmax ----------------
__global__ void out_softmax(const float* __restrict__ newh, const float* __restrict__ W_out,
                            const float* __restrict__ b_out, float* __restrict__ out) {
    int b = blockIdx.x;
    int tid = threadIdx.x;       // 128
    __shared__ float sh[HID];
    __shared__ float logit[VOC];
    __shared__ float s_max, s_inv;
    for (int k = tid; k < HID; k += 128) sh[k] = newh[b*HID + k];
    __syncthreads();
    if (tid < VOC) {
        float s = b_out[tid];
        for (int k = 0; k < HID; k++) s += sh[k] * W_out[k*VOC + tid];
        logit[tid] = s;
    }
    __syncthreads();
    if (tid == 0) {
        float m = -1e30f;
        for (int c = 0; c < VOC; c++) m = fmaxf(m, logit[c]);
        float sum = 0.f;
        for (int c = 0; c < VOC; c++) sum += expf(logit[c] - m);
        s_max = m; s_inv = 1.f / sum;
    }
    __syncthreads();
    if (tid < VOC)
        out[b*VOC + tid] = expf(logit[tid] - s_max) * s_inv;
}

// ---------------- launch ----------------
extern "C" void kernel_launch(void* const* d_in, const int* in_sizes, int n_in,
                              void* d_out, int out_size) {
    const float* in_char = (const float*)d_in[0];
    const float* hidden  = (const float*)d_in[1];
    const float* enc     = (const float*)d_in[2];
    const float* W_hp    = (const float*)d_in[3];
    const float* b_hp    = (const float*)d_in[4];
    const float* W_ep    = (const float*)d_in[5];
    const float* b_ep    = (const float*)d_in[6];
    const float* w_v     = (const float*)d_in[7];
    const float* W_cs    = (const float*)d_in[9];
    const float* b_cs    = (const float*)d_in[10];
    const float* emb     = (const float*)d_in[11];
    const float* W_ih    = (const float*)d_in[12];
    const float* b_ih    = (const float*)d_in[13];
    const float* W_hh    = (const float*)d_in[14];
    const float* b_hh    = (const float*)d_in[15];
    const float* W_out   = (const float*)d_in[16];
    const float* b_out   = (const float*)d_in[17];

    float* out = (float*)d_out;
    float* out_output = out;                       // 256*83
    float* out_newh   = out + BSZ*VOC;             // 256*512
    float* out_aw     = out + BSZ*VOC + BSZ*HID;   // 256*600

    float *p_hadd, *p_ctx, *p_ctxp, *p_indec, *p_gi, *p_gh;
    cudaGetSymbolAddress((void**)&p_hadd,  d_hadd);
    cudaGetSymbolAddress((void**)&p_ctx,   d_context);
    cudaGetSymbolAddress((void**)&p_ctxp,  d_ctxp);
    cudaGetSymbolAddress((void**)&p_indec, d_indec);
    cudaGetSymbolAddress((void**)&p_gi,    d_gi);
    cudaGetSymbolAddress((void**)&p_gh,    d_gh);

    cudaFuncSetAttribute(attn_mma_kernel,
                         cudaFuncAttributeMaxDynamicSharedMemorySize, ATTN_SMEM);

    // 1. prep: transpose W_ep; zero accumulators
    prep_wepT<<<256, 256>>>(W_ep);
    zero_scores<<<(BSZ*TSZ + 255)/256, 256>>>();
    zero_ctx<<<(BSZ*HID + 511)/512, 512>>>();

    // 2. hadd = hidden@W_hp + b_hp + b_ep
    { dim3 g(HID/64, BSZ/64); sgemm_bias<<<g, 256>>>(hidden, W_hp, b_hp, b_ep, p_hadd, BSZ, HID, HID); }

    // 3. gh = hidden@W_hh + b_hh
    { dim3 g(NGATE/64, BSZ/64); sgemm_bias<<<g, 256>>>(hidden, W_hh, b_hh, nullptr, p_gh, BSZ, NGATE, HID); }

    // 4. fused attention-score GEMM on mma.sync tf32 (b_v cancels in softmax)
    { dim3 g((BSZ*TSZ)/128, HID/128); attn_mma_kernel<<<g, 256, ATTN_SMEM>>>(enc, w_v); }

    // 5. softmax -> attn_weights (into d_out)
    softmax_attn<<<BSZ, 256>>>(out_aw);

    // 6. context = weighted sum of enc (4-way T split)
    { dim3 g(BSZ, 4); context_kernel<<<g, HID>>>(enc, out_aw); }

    // 7. ctxp = context@W_cs + b_cs
    { dim3 g((250 + 63)/64, BSZ/64); sgemm_bias<<<g, 256>>>(p_ctx, W_cs, b_cs, nullptr, p_ctxp, BSZ, 250, HID); }

    // 8. in_dec = [emb[argmax(in_char)], ctxp]
    build_indec<<<BSZ, 64>>>(in_char, emb);

    // 9. gi = in_dec@W_ih + b_ih
    { dim3 g(NGATE/64, BSZ/64); sgemm_bias<<<g, 256>>>(p_indec, W_ih, b_ih, nullptr, p_gi, BSZ, NGATE, 300); }

    // 10. GRU gates -> new_h (into d_out)
    gru_gate<<<(BSZ*HID)/256, 256>>>(hidden, out_newh);

    // 11. output = softmax(new_h @ W_out + b_out)
    out_softmax<<<BSZ, 128>>>(out_newh, W_out, b_out, out_output);
}